// round 2
// baseline (speedup 1.0000x reference)
#include <cuda_runtime.h>

#define NPROP 1024
#define NCLS  81
#define NC2   80        // foreground classes
#define KDET  100
#define FDIM  1024
#define IMG_W 1216.0f
#define IMG_H 800.0f
#define SCORE_TH 0.05f
#define NMS_TH 0.5f
#define BBOX_CLIP 4.135166556742356f   // log(1000/16)

// ---------- device scratch (static device globals are allowed) ----------
__device__ float2 g_rowstats[NPROP];                 // (rowmax, rowsum) of softmax
__device__ float  g_cand_box[NC2 * NPROP * 4];       // indexed by flat f = c*NPROP + p
__device__ int    g_cand_orig[NC2 * NPROP];
__device__ unsigned long long g_plist[NC2 * NPROP];  // packed kept candidates
__device__ int    g_pcnt;
__device__ int    g_sel_orig[KDET];

// ---------- kernel 1: per-row softmax stats (max, sum of exp) ----------
__global__ void rowstats_kernel(const float* __restrict__ logits) {
    if (blockIdx.x == 0 && threadIdx.x == 0) g_pcnt = 0;   // reset global counter
    const int row  = blockIdx.x * 8 + (threadIdx.x >> 5);  // 8 warps per block
    const int lane = threadIdx.x & 31;
    if (row >= NPROP) return;
    const float* lp = logits + (size_t)row * NCLS;
    float mx = -3.4e38f;
    for (int j = lane; j < NCLS; j += 32) mx = fmaxf(mx, lp[j]);
    for (int o = 16; o; o >>= 1) mx = fmaxf(mx, __shfl_xor_sync(0xffffffffu, mx, o));
    float sum = 0.0f;
    for (int j = lane; j < NCLS; j += 32) sum += expf(lp[j] - mx);
    for (int o = 16; o; o >>= 1) sum += __shfl_xor_sync(0xffffffffu, sum, o);
    if (lane == 0) g_rowstats[row] = make_float2(mx, sum);
}

// ---------- kernel 2: per-class compact + sort + decode + NMS + emit ----------
__global__ void class_nms_kernel(const float* __restrict__ logits,
                                 const float* __restrict__ box_reg,
                                 const float* __restrict__ proposals) {
    const int c = blockIdx.x;             // foreground class 0..79 (real class c+1)
    const int tid = threadIdx.x, bd = blockDim.x;   // 256

    __shared__ int s_cnt;
    __shared__ unsigned long long s_key[NPROP];
    __shared__ int   s_idx[NPROP];
    __shared__ float s_x1[NPROP], s_y1[NPROP], s_x2[NPROP], s_y2[NPROP], s_area[NPROP];
    __shared__ unsigned char s_keep[NPROP];

    if (tid == 0) s_cnt = 0;
    __syncthreads();

    // Phase A: score this class's column; compact valid entries
    for (int n = tid; n < NPROP; n += bd) {
        float2 st = g_rowstats[n];
        float l = logits[(size_t)n * NCLS + (c + 1)];
        float p = expf(l - st.x) / st.y;       // same op order as jax softmax
        if (p > SCORE_TH) {
            int pos = atomicAdd(&s_cnt, 1);
            // descending sort key: score bits major, (N-1-n) minor => lower n wins ties
            s_key[pos] = ((unsigned long long)__float_as_uint(p) << 32) |
                         (unsigned)(NPROP - 1 - n);
        }
    }
    __syncthreads();
    const int M = s_cnt;
    int Mp = 1; while (Mp < M) Mp <<= 1;
    for (int p = M + tid; p < Mp; p += bd) s_key[p] = 0ULL;
    __syncthreads();

    // Phase B: bitonic sort descending on s_key[0..Mp)
    if (M > 1) {
        for (int k = 2; k <= Mp; k <<= 1) {
            for (int j = k >> 1; j > 0; j >>= 1) {
                for (int i = tid; i < Mp; i += bd) {
                    int ixj = i ^ j;
                    if (ixj > i) {
                        unsigned long long a = s_key[i], b = s_key[ixj];
                        bool descBlock = ((i & k) == 0);
                        if (descBlock ? (a < b) : (a > b)) { s_key[i] = b; s_key[ixj] = a; }
                    }
                }
                __syncthreads();
            }
        }
    }

    // Phase C: unpack + decode + clip (valid entries only)
    for (int p = tid; p < M; p += bd) {
        unsigned long long key = s_key[p];
        int n = (NPROP - 1) - (int)(key & 0xFFFFFFFFULL);
        s_idx[p] = n;

        float4 pb = ((const float4*)proposals)[n];
        float w = pb.z - pb.x + 1.0f, h = pb.w - pb.y + 1.0f;
        float cx = pb.x + 0.5f * w,  cy = pb.y + 0.5f * h;
        const float* r = box_reg + (size_t)n * (NCLS * 4) + (c + 1) * 4;
        float dx = r[0] / 10.0f, dy = r[1] / 10.0f;
        float dw = fminf(r[2] / 5.0f, BBOX_CLIP);
        float dh = fminf(r[3] / 5.0f, BBOX_CLIP);
        float pcx = dx * w + cx, pcy = dy * h + cy;
        float pw = expf(dw) * w, ph = expf(dh) * h;
        float x1 = pcx - 0.5f * pw, y1 = pcy - 0.5f * ph;
        float x2 = pcx + 0.5f * pw - 1.0f, y2 = pcy + 0.5f * ph - 1.0f;
        x1 = fminf(fmaxf(x1, 0.0f), IMG_W - 1.0f);
        y1 = fminf(fmaxf(y1, 0.0f), IMG_H - 1.0f);
        x2 = fminf(fmaxf(x2, 0.0f), IMG_W - 1.0f);
        y2 = fminf(fmaxf(y2, 0.0f), IMG_H - 1.0f);
        s_x1[p] = x1; s_y1[p] = y1; s_x2[p] = x2; s_y2[p] = y2;
        s_area[p] = (x2 - x1 + 1.0f) * (y2 - y1 + 1.0f);
        s_keep[p] = 1;
    }
    __syncthreads();

    // Phase D: sequential hard NMS (descending score order)
    for (int i = 0; i < M; i++) {
        if (s_keep[i]) {                       // uniform across block
            float xi1 = s_x1[i], yi1 = s_y1[i], xi2 = s_x2[i], yi2 = s_y2[i], ai = s_area[i];
            for (int j = i + 1 + tid; j < M; j += bd) {
                if (s_keep[j]) {
                    float xx1 = fmaxf(xi1, s_x1[j]);
                    float yy1 = fmaxf(yi1, s_y1[j]);
                    float xx2 = fminf(xi2, s_x2[j]);
                    float yy2 = fminf(yi2, s_y2[j]);
                    float ww = fmaxf(xx2 - xx1 + 1.0f, 0.0f);
                    float hh = fmaxf(yy2 - yy1 + 1.0f, 0.0f);
                    float inter = ww * hh;
                    float iou = inter / (ai + s_area[j] - inter);
                    if (iou > NMS_TH) s_keep[j] = 0;
                }
            }
        }
        __syncthreads();
    }

    // Phase E: emit kept candidates (sorted position p -> flat index matches reference)
    for (int p = tid; p < M; p += bd) {
        if (s_keep[p]) {
            int f = c * NPROP + p;
            unsigned sbits = (unsigned)(s_key[p] >> 32);
            int gp = atomicAdd(&g_pcnt, 1);
            // descending key; lower flat index wins ties (matches lax.top_k)
            g_plist[gp] = ((unsigned long long)sbits << 32) | (unsigned)(0x7FFFFFFF - f);
            g_cand_orig[f] = s_idx[p];
            ((float4*)g_cand_box)[f] = make_float4(s_x1[p], s_y1[p], s_x2[p], s_y2[p]);
        }
    }
}

// ---------- bitonic sort (descending) of 2048 u64 keys, 1024 threads ----------
__device__ __forceinline__ void bitonic2048(unsigned long long* s_key, int tid) {
    for (int k = 2; k <= 2048; k <<= 1) {
        for (int j = k >> 1; j > 0; j >>= 1) {
            for (int i = tid; i < 2048; i += 1024) {
                int ixj = i ^ j;
                if (ixj > i) {
                    unsigned long long a = s_key[i], b = s_key[ixj];
                    bool descBlock = ((i & k) == 0);
                    if (descBlock ? (a < b) : (a > b)) { s_key[i] = b; s_key[ixj] = a; }
                }
            }
            __syncthreads();
        }
    }
}

// ---------- kernel 3: global top-K (chunked carry) + boxes/scores/labels ----------
__global__ void topk_kernel(float* __restrict__ d_out) {
    const int tid = threadIdx.x;          // 1024 threads, single block
    __shared__ unsigned long long s_key[2048];

    int P = g_pcnt;
    if (P > NC2 * NPROP) P = NC2 * NPROP;

    // first chunk: up to 2048 candidates
    for (int i = tid; i < 2048; i += 1024)
        s_key[i] = (i < P) ? g_plist[i] : 0ULL;
    __syncthreads();
    if (P > 1) bitonic2048(s_key, tid);

    // remaining chunks: carry sorted top-128, refill 1920, re-sort
    int pos = 2048;
    while (pos < P) {
        int cnt = P - pos; if (cnt > 1920) cnt = 1920;
        for (int i = tid; i < 1920; i += 1024)
            s_key[128 + i] = (i < cnt) ? g_plist[pos + i] : 0ULL;
        __syncthreads();
        bitonic2048(s_key, tid);
        pos += 1920;
    }

    // write boxes / scores / labels; stash orig index for feature gather
    if (tid < KDET) {
        unsigned long long key = s_key[tid];
        float sc = 0.0f; int label = 0; int orig = -1;
        float4 bx = make_float4(0.f, 0.f, 0.f, 0.f);
        if (key) {
            sc = __uint_as_float((unsigned)(key >> 32));
            int f = 0x7FFFFFFF - (int)(key & 0xFFFFFFFFULL);
            bx = ((const float4*)g_cand_box)[f];
            label = (f >> 10) + 1;              // f / NPROP + 1
            orig = g_cand_orig[f];
        }
        d_out[tid * 4 + 0] = bx.x;
        d_out[tid * 4 + 1] = bx.y;
        d_out[tid * 4 + 2] = bx.z;
        d_out[tid * 4 + 3] = bx.w;
        d_out[KDET * 4 + tid] = sc;                                  // scores
        d_out[KDET * 4 + KDET + KDET * FDIM + tid] = (float)label;   // labels
        g_sel_orig[tid] = orig;
    }
}

// ---------- kernel 4: feature gather ----------
__global__ void feat_kernel(const float* __restrict__ features, float* __restrict__ d_out) {
    const int k = blockIdx.x;             // 100 blocks
    const int t = threadIdx.x;            // 256 threads -> 256 float4 = 1024 floats
    int orig = g_sel_orig[k];
    float4* dst = (float4*)(d_out + KDET * 4 + KDET + (size_t)k * FDIM);
    if (orig >= 0) {
        const float4* src = (const float4*)(features + (size_t)orig * FDIM);
        dst[t] = src[t];
    } else {
        dst[t] = make_float4(0.f, 0.f, 0.f, 0.f);
    }
}

// ---------- launch ----------
extern "C" void kernel_launch(void* const* d_in, const int* in_sizes, int n_in,
                              void* d_out, int out_size) {
    const float* logits  = (const float*)d_in[0];   // [N, 81]
    const float* box_reg = (const float*)d_in[1];   // [N, 324]
    const float* props   = (const float*)d_in[2];   // [N, 4]
    const float* feats   = (const float*)d_in[3];   // [N, 1024]
    float* out = (float*)d_out;                     // 103000 floats

    rowstats_kernel<<<NPROP / 8, 256>>>(logits);
    class_nms_kernel<<<NC2, 256>>>(logits, box_reg, props);
    topk_kernel<<<1, 1024>>>(out);
    feat_kernel<<<KDET, 256>>>(feats, out);
}

// round 3
// speedup vs baseline: 2.3797x; 2.3797x over previous
#include <cuda_runtime.h>

#define NPROP 1024
#define NCLS  81
#define NC2   80        // foreground classes
#define KDET  100
#define FDIM  1024
#define IMG_W 1216.0f
#define IMG_H 800.0f
#define SCORE_TH 0.05f
#define NMS_TH 0.5f
#define BBOX_CLIP 4.135166556742356f   // log(1000/16)

#define MMASK 256       // bitmask-NMS fast path capacity
#define WMASK 4         // 256/64 words

// ---------- device scratch ----------
__device__ float2 g_rowstats[NPROP];                 // (rowmax, rowsum)
__device__ float  g_cand_box[NC2 * NPROP * 4];       // flat f = c*NPROP + sorted_pos
__device__ int    g_cand_orig[NC2 * NPROP];
__device__ unsigned long long g_plist[NC2 * NPROP];  // packed kept candidates
__device__ int    g_pcnt;
__device__ int    g_sel_orig[KDET];

// ---------- kernel 1: per-row softmax stats ----------
__global__ void rowstats_kernel(const float* __restrict__ logits) {
    if (blockIdx.x == 0 && threadIdx.x == 0) g_pcnt = 0;
    const int row  = blockIdx.x * 8 + (threadIdx.x >> 5);
    const int lane = threadIdx.x & 31;
    if (row >= NPROP) return;
    const float* lp = logits + (size_t)row * NCLS;
    float mx = -3.4e38f;
    for (int j = lane; j < NCLS; j += 32) mx = fmaxf(mx, lp[j]);
    for (int o = 16; o; o >>= 1) mx = fmaxf(mx, __shfl_xor_sync(0xffffffffu, mx, o));
    float sum = 0.0f;
    for (int j = lane; j < NCLS; j += 32) sum += expf(lp[j] - mx);
    for (int o = 16; o; o >>= 1) sum += __shfl_xor_sync(0xffffffffu, sum, o);
    if (lane == 0) g_rowstats[row] = make_float2(mx, sum);
}

// ---------- kernel 2: per-class score + sort + decode + bitmask NMS ----------
__global__ void class_nms_kernel(const float* __restrict__ logits,
                                 const float* __restrict__ box_reg,
                                 const float* __restrict__ proposals) {
    const int c = blockIdx.x;
    const int tid = threadIdx.x, bd = blockDim.x;   // 256

    __shared__ int s_cnt;
    __shared__ unsigned long long s_key[NPROP];                  // 8KB
    __shared__ float s_x1[NPROP], s_y1[NPROP], s_x2[NPROP], s_y2[NPROP], s_area[NPROP]; // 20KB
    __shared__ unsigned long long s_mask[MMASK * WMASK];         // 8KB
    __shared__ unsigned long long s_kw[WMASK];
    __shared__ unsigned char s_keep[NPROP];                      // 1KB (fallback)

    if (tid == 0) s_cnt = 0;
    __syncthreads();

    // Phase A: score this class's column; compact valid entries
    for (int n = tid; n < NPROP; n += bd) {
        float2 st = g_rowstats[n];
        float l = logits[(size_t)n * NCLS + (c + 1)];
        float p = expf(l - st.x) / st.y;
        if (p > SCORE_TH) {
            int pos = atomicAdd(&s_cnt, 1);
            s_key[pos] = ((unsigned long long)__float_as_uint(p) << 32) |
                         (unsigned)(NPROP - 1 - n);   // lower n wins ties
        }
    }
    __syncthreads();
    const int M = s_cnt;
    if (M == 0) return;
    int Mp = 1; while (Mp < M) Mp <<= 1;
    for (int p = M + tid; p < Mp; p += bd) s_key[p] = 0ULL;
    __syncthreads();

    // Phase B: bitonic sort descending
    if (M > 1) {
        for (int k = 2; k <= Mp; k <<= 1) {
            for (int j = k >> 1; j > 0; j >>= 1) {
                for (int i = tid; i < Mp; i += bd) {
                    int ixj = i ^ j;
                    if (ixj > i) {
                        unsigned long long a = s_key[i], b = s_key[ixj];
                        bool descBlock = ((i & k) == 0);
                        if (descBlock ? (a < b) : (a > b)) { s_key[i] = b; s_key[ixj] = a; }
                    }
                }
                __syncthreads();
            }
        }
    }

    // Phase C: decode + clip valid entries
    for (int p = tid; p < M; p += bd) {
        int n = (NPROP - 1) - (int)(s_key[p] & 0xFFFFFFFFULL);
        float4 pb = __ldg((const float4*)proposals + n);
        float w = pb.z - pb.x + 1.0f, h = pb.w - pb.y + 1.0f;
        float cx = pb.x + 0.5f * w,  cy = pb.y + 0.5f * h;
        float4 r = __ldg((const float4*)(box_reg + (size_t)n * (NCLS * 4) + (c + 1) * 4));
        float dx = r.x / 10.0f, dy = r.y / 10.0f;
        float dw = fminf(r.z / 5.0f, BBOX_CLIP);
        float dh = fminf(r.w / 5.0f, BBOX_CLIP);
        float pcx = dx * w + cx, pcy = dy * h + cy;
        float pw = expf(dw) * w, ph = expf(dh) * h;
        float x1 = pcx - 0.5f * pw, y1 = pcy - 0.5f * ph;
        float x2 = pcx + 0.5f * pw - 1.0f, y2 = pcy + 0.5f * ph - 1.0f;
        x1 = fminf(fmaxf(x1, 0.0f), IMG_W - 1.0f);
        y1 = fminf(fmaxf(y1, 0.0f), IMG_H - 1.0f);
        x2 = fminf(fmaxf(x2, 0.0f), IMG_W - 1.0f);
        y2 = fminf(fmaxf(y2, 0.0f), IMG_H - 1.0f);
        s_x1[p] = x1; s_y1[p] = y1; s_x2[p] = x2; s_y2[p] = y2;
        s_area[p] = (x2 - x1 + 1.0f) * (y2 - y1 + 1.0f);
        s_keep[p] = 1;
    }
    __syncthreads();

    const bool fastpath = (M <= MMASK);
    if (fastpath) {
        // Phase D-fast: parallel suppression bitmask, then barrier-free bit reduce
        const int nwords = M * WMASK;
        for (int idx = tid; idx < nwords; idx += bd) {
            int i = idx >> 2, w = idx & 3;
            float xi1 = s_x1[i], yi1 = s_y1[i], xi2 = s_x2[i], yi2 = s_y2[i], ai = s_area[i];
            unsigned long long bits = 0ULL;
            int jlo = w << 6;
            int jhi = jlo + 64; if (jhi > M) jhi = M;
            int j0 = (i + 1 > jlo) ? i + 1 : jlo;
            for (int j = j0; j < jhi; j++) {
                float xx1 = fmaxf(xi1, s_x1[j]);
                float yy1 = fmaxf(yi1, s_y1[j]);
                float xx2 = fminf(xi2, s_x2[j]);
                float yy2 = fminf(yi2, s_y2[j]);
                float ww = fmaxf(xx2 - xx1 + 1.0f, 0.0f);
                float hh = fmaxf(yy2 - yy1 + 1.0f, 0.0f);
                float inter = ww * hh;
                float iou = inter / (ai + s_area[j] - inter);
                if (iou > NMS_TH) bits |= 1ULL << (j - jlo);
            }
            s_mask[idx] = bits;
        }
        __syncthreads();
        if (tid == 0) {
            unsigned long long kw0 = ~0ULL, kw1 = ~0ULL, kw2 = ~0ULL, kw3 = ~0ULL;
            for (int i = 0; i < M; i++) {
                unsigned long long ow = (i < 64) ? kw0 : (i < 128) ? kw1 : (i < 192) ? kw2 : kw3;
                if ((ow >> (i & 63)) & 1ULL) {
                    const unsigned long long* row = &s_mask[i << 2];
                    kw0 &= ~row[0]; kw1 &= ~row[1]; kw2 &= ~row[2]; kw3 &= ~row[3];
                }
            }
            s_kw[0] = kw0; s_kw[1] = kw1; s_kw[2] = kw2; s_kw[3] = kw3;
        }
        __syncthreads();
    } else {
        // Phase D-fallback: sequential barrier NMS (M > 256, statistically rare)
        for (int i = 0; i < M; i++) {
            if (s_keep[i]) {
                float xi1 = s_x1[i], yi1 = s_y1[i], xi2 = s_x2[i], yi2 = s_y2[i], ai = s_area[i];
                for (int j = i + 1 + tid; j < M; j += bd) {
                    if (s_keep[j]) {
                        float xx1 = fmaxf(xi1, s_x1[j]);
                        float yy1 = fmaxf(yi1, s_y1[j]);
                        float xx2 = fminf(xi2, s_x2[j]);
                        float yy2 = fminf(yi2, s_y2[j]);
                        float ww = fmaxf(xx2 - xx1 + 1.0f, 0.0f);
                        float hh = fmaxf(yy2 - yy1 + 1.0f, 0.0f);
                        float inter = ww * hh;
                        float iou = inter / (ai + s_area[j] - inter);
                        if (iou > NMS_TH) s_keep[j] = 0;
                    }
                }
            }
            __syncthreads();
        }
    }

    // Phase E: emit kept candidates
    for (int p = tid; p < M; p += bd) {
        bool kept = fastpath ? ((s_kw[p >> 6] >> (p & 63)) & 1ULL) : (bool)s_keep[p];
        if (kept) {
            int f = c * NPROP + p;
            unsigned long long key = s_key[p];
            unsigned sbits = (unsigned)(key >> 32);
            int n = (NPROP - 1) - (int)(key & 0xFFFFFFFFULL);
            int gp = atomicAdd(&g_pcnt, 1);
            g_plist[gp] = ((unsigned long long)sbits << 32) | (unsigned)(0x7FFFFFFF - f);
            g_cand_orig[f] = n;
            ((float4*)g_cand_box)[f] = make_float4(s_x1[p], s_y1[p], s_x2[p], s_y2[p]);
        }
    }
}

// ---------- generic in-smem bitonic sort (descending), all threads call ----------
__device__ __forceinline__ void bitonic_desc(unsigned long long* key, int Sp, int tid, int nthr) {
    for (int k = 2; k <= Sp; k <<= 1) {
        for (int j = k >> 1; j > 0; j >>= 1) {
            for (int i = tid; i < Sp; i += nthr) {
                int ixj = i ^ j;
                if (ixj > i) {
                    unsigned long long a = key[i], b = key[ixj];
                    bool descBlock = ((i & k) == 0);
                    if (descBlock ? (a < b) : (a > b)) { key[i] = b; key[ixj] = a; }
                }
            }
            __syncthreads();
        }
    }
}

// ---------- kernel 3: radix-select top-K + boxes/scores/labels ----------
__global__ void topk_kernel(float* __restrict__ d_out) {
    const int tid = threadIdx.x;          // 1024 threads
    __shared__ int s_histA[1024];
    __shared__ int s_histB[1024];
    __shared__ unsigned long long s_key[2048];
    __shared__ int s_B, s_cnt;

    int P = g_pcnt;
    if (P > NC2 * NPROP) P = NC2 * NPROP;

    s_histA[tid] = 0;
    s_key[tid] = 0ULL; s_key[tid + 1024] = 0ULL;
    if (tid == 0) { s_B = 0; s_cnt = 0; }
    __syncthreads();

    // pass 1: histogram of score-bit high bits (bins cover (0.05, 1.0])
    for (int i = tid; i < P; i += 1024) {
        unsigned sb = (unsigned)(g_plist[i] >> 32);
        int b = (int)(sb >> 16) - 0x3D40;
        b = b < 0 ? 0 : (b > 1023 ? 1023 : b);
        atomicAdd(&s_histA[b], 1);
    }
    __syncthreads();

    // suffix-inclusive scan (Hillis-Steele, double buffer)
    int* src = s_histA; int* dst = s_histB;
    for (int st = 1; st < 1024; st <<= 1) {
        int v = src[tid] + ((tid + st < 1024) ? src[tid + st] : 0);
        dst[tid] = v;
        __syncthreads();
        int* t = src; src = dst; dst = t;
    }
    {   // threshold bin: smallest suffix-count >= K
        int sfx = src[tid];
        int nxt = (tid < 1023) ? src[tid + 1] : 0;
        if (sfx >= KDET && nxt < KDET) s_B = tid;
    }
    __syncthreads();
    const int B = s_B;

    // pass 2: collect candidates in bins >= B
    for (int i = tid; i < P; i += 1024) {
        unsigned long long key = g_plist[i];
        int b = (int)((unsigned)(key >> 32) >> 16) - 0x3D40;
        b = b < 0 ? 0 : (b > 1023 ? 1023 : b);
        if (b >= B) {
            int p = atomicAdd(&s_cnt, 1);
            if (p < 2048) s_key[p] = key;
        }
    }
    __syncthreads();
    int cnt = s_cnt;

    if (cnt <= 2048) {
        int Sp = 128; while (Sp < cnt) Sp <<= 1;
        bitonic_desc(s_key, Sp, tid, 1024);
    } else {
        // pathological tie overflow: exact chunked-carry over all candidates
        for (int i = tid; i < 2048; i += 1024) s_key[i] = (i < P) ? g_plist[i] : 0ULL;
        __syncthreads();
        bitonic_desc(s_key, 2048, tid, 1024);
        int pos = 2048;
        while (pos < P) {
            int c2 = P - pos; if (c2 > 1920) c2 = 1920;
            for (int i = tid; i < 1920; i += 1024)
                s_key[128 + i] = (i < c2) ? g_plist[pos + i] : 0ULL;
            __syncthreads();
            bitonic_desc(s_key, 2048, tid, 1024);
            pos += 1920;
        }
    }

    // outputs
    if (tid < KDET) {
        unsigned long long key = s_key[tid];
        float sc = 0.0f; int label = 0; int orig = -1;
        float4 bx = make_float4(0.f, 0.f, 0.f, 0.f);
        if (key) {
            sc = __uint_as_float((unsigned)(key >> 32));
            int f = 0x7FFFFFFF - (int)(key & 0xFFFFFFFFULL);
            bx = ((const float4*)g_cand_box)[f];
            label = (f >> 10) + 1;
            orig = g_cand_orig[f];
        }
        d_out[tid * 4 + 0] = bx.x;
        d_out[tid * 4 + 1] = bx.y;
        d_out[tid * 4 + 2] = bx.z;
        d_out[tid * 4 + 3] = bx.w;
        d_out[KDET * 4 + tid] = sc;
        d_out[KDET * 4 + KDET + KDET * FDIM + tid] = (float)label;
        g_sel_orig[tid] = orig;
    }
}

// ---------- kernel 4: feature gather (MLP=2 per thread) ----------
__global__ void feat_kernel(const float* __restrict__ features, float* __restrict__ d_out) {
    const int k = blockIdx.x;             // 100 blocks
    const int t = threadIdx.x;            // 128 threads, 2 float4 each
    int orig = g_sel_orig[k];
    float4* dst = (float4*)(d_out + KDET * 4 + KDET + (size_t)k * FDIM);
    if (orig >= 0) {
        const float4* src = (const float4*)(features + (size_t)orig * FDIM);
        float4 a = __ldg(src + t);
        float4 b = __ldg(src + t + 128);
        dst[t] = a; dst[t + 128] = b;
    } else {
        dst[t] = make_float4(0.f, 0.f, 0.f, 0.f);
        dst[t + 128] = make_float4(0.f, 0.f, 0.f, 0.f);
    }
}

// ---------- launch ----------
extern "C" void kernel_launch(void* const* d_in, const int* in_sizes, int n_in,
                              void* d_out, int out_size) {
    const float* logits  = (const float*)d_in[0];   // [N, 81]
    const float* box_reg = (const float*)d_in[1];   // [N, 324]
    const float* props   = (const float*)d_in[2];   // [N, 4]
    const float* feats   = (const float*)d_in[3];   // [N, 1024]
    float* out = (float*)d_out;

    rowstats_kernel<<<NPROP / 8, 256>>>(logits);
    class_nms_kernel<<<NC2, 256>>>(logits, box_reg, props);
    topk_kernel<<<1, 1024>>>(out);
    feat_kernel<<<KDET, 128>>>(feats, out);
}